// round 1
// baseline (speedup 1.0000x reference)
#include <cuda_runtime.h>
#include <math.h>

#define BB 32768
#define EE 9
#define RANKK 50
#define DD 450           // E*RANK
#define NPAIR 225        // E * RANK/2
#define WPB 4            // warps per block
#define ITER 8           // elements per warp
#define NBLOCKS (BB / (WPB * ITER))   // 1024

// global scratch (no allocation allowed)
__device__ double g_load[EE];
__device__ double g_imp[EE];

__device__ __forceinline__ float softplusf(float x) {
    if (x > 20.0f) return x;
    return log1pf(expf(x));
}
__device__ __forceinline__ float phif(float z) {
    return 0.5f * (1.0f + erff(z * 0.70710678118654752f));
}

__global__ void init_kernel() {
    int t = threadIdx.x;
    if (t < EE) { g_load[t] = 0.0; g_imp[t] = 0.0; }
}

__global__ __launch_bounds__(128) void swise_main_kernel(
    const int* __restrict__ queries, const int* __restrict__ these_queries,
    const float* __restrict__ entity, const float* __restrict__ rel,
    const float* __restrict__ rel_diag,
    const float* __restrict__ bh, const float* __restrict__ bt,
    const float* __restrict__ c_param,
    const float* __restrict__ cnn_w, const float* __restrict__ cnn_b,
    const float* __restrict__ h2e_w, const float* __restrict__ h2e_b,
    const float* __restrict__ cnnn_w, const float* __restrict__ cnnn_b,
    const float* __restrict__ h2en_w, const float* __restrict__ h2en_b,
    const float* __restrict__ noise, float* __restrict__ y_out)
{
    __shared__ float sx[WPB][1350];
    __shared__ float swc[25], swn[25];
    __shared__ float sh2e[EE * 128], sh2en[EE * 128];
    __shared__ float sbc[2];
    __shared__ float sbe[EE], sben[EE];
    __shared__ float s_load[EE], s_imp[EE];

    const int tid = threadIdx.x;
    for (int i = tid; i < 25; i += blockDim.x) { swc[i] = cnn_w[i]; swn[i] = cnnn_w[i]; }
    for (int i = tid; i < EE * 128; i += blockDim.x) { sh2e[i] = h2e_w[i]; sh2en[i] = h2en_w[i]; }
    if (tid == 0) { sbc[0] = cnn_b[0]; sbc[1] = cnnn_b[0]; }
    if (tid < EE) { sbe[tid] = h2e_b[tid]; sben[tid] = h2en_b[tid];
                    s_load[tid] = 0.0f; s_imp[tid] = 0.0f; }
    __syncthreads();

    const int warp = tid >> 5, lane = tid & 31;
    float* sxw = sx[warp];
    const int gw = blockIdx.x * WPB + warp;

    for (int it = 0; it < ITER; it++) {
        const int b = gw * ITER + it;
        const int q0 = queries[3 * b];
        const int q1 = queries[3 * b + 1];
        const int t2 = these_queries[3 * b + 2];

        // ---- stage x = [head(450) | rel(900)] into shared (coalesced float2) ----
        const float2* hrow = (const float2*)(entity + (size_t)q0 * DD);
        for (int i = lane; i < 225; i += 32) {
            float2 v = __ldg(hrow + i);
            sxw[2 * i] = v.x; sxw[2 * i + 1] = v.y;
        }
        const float2* rrow = (const float2*)(rel + (size_t)q1 * (2 * DD));
        for (int i = lane; i < 450; i += 32) {
            float2 v = __ldg(rrow + i);
            sxw[DD + 2 * i] = v.x; sxw[DD + 2 * i + 1] = v.y;
        }
        __syncwarp();

        // ---- conv (stride 3, VALID, 8x16=128 outputs) + fused linear partials ----
        float clean[EE], stdv[EE];
        #pragma unroll
        for (int e = 0; e < EE; e++) { clean[e] = 0.0f; stdv[e] = 0.0f; }
        #pragma unroll
        for (int j = 0; j < 4; j++) {
            const int f = 32 * j + lane;
            const int oh = f >> 4, ow = f & 15;
            const float* base = sxw + (oh * 3) * RANKK + ow * 3;
            float ac = 0.0f, an = 0.0f;
            #pragma unroll
            for (int kh = 0; kh < 5; kh++) {
                #pragma unroll
                for (int kw = 0; kw < 5; kw++) {
                    const float xv = base[kh * RANKK + kw];
                    ac = fmaf(xv, swc[kh * 5 + kw], ac);
                    an = fmaf(xv, swn[kh * 5 + kw], an);
                }
            }
            ac += sbc[0]; an += sbc[1];
            #pragma unroll
            for (int e = 0; e < EE; e++) {
                clean[e] = fmaf(ac, sh2e[e * 128 + f], clean[e]);
                stdv[e]  = fmaf(an, sh2en[e * 128 + f], stdv[e]);
            }
        }
        // butterfly reduce both 9-vectors (result uniform across lanes)
        #pragma unroll
        for (int off = 16; off > 0; off >>= 1) {
            #pragma unroll
            for (int e = 0; e < EE; e++) {
                clean[e] += __shfl_xor_sync(0xffffffffu, clean[e], off);
                stdv[e]  += __shfl_xor_sync(0xffffffffu, stdv[e], off);
            }
        }

        // ---- gating (uniform across lanes) ----
        float noisyv[EE];
        #pragma unroll
        for (int e = 0; e < EE; e++) {
            clean[e] += sbe[e];
            stdv[e] = softplusf(stdv[e] + sben[e]) + 0.01f;
            noisyv[e] = fmaf(noise[(size_t)b * EE + e], stdv[e], clean[e]);
        }
        // top-3 (strict >, first index wins — matches lax.top_k tie-break)
        int i1 = 0; float v1 = noisyv[0];
        #pragma unroll
        for (int e = 1; e < EE; e++) if (noisyv[e] > v1) { v1 = noisyv[e]; i1 = e; }
        int i2 = -1; float v2 = -INFINITY;
        #pragma unroll
        for (int e = 0; e < EE; e++) if (e != i1 && noisyv[e] > v2) { v2 = noisyv[e]; i2 = e; }
        float v3 = -INFINITY;
        #pragma unroll
        for (int e = 0; e < EE; e++) if (e != i1 && e != i2 && noisyv[e] > v3) v3 = noisyv[e];

        // gates = softmax([v1, v2])
        const float t_e = expf(v2 - v1);
        const float g1 = 1.0f / (1.0f + t_e);
        const float g2 = t_e / (1.0f + t_e);

        // prob per expert; accumulate load & importance (lane 0 -> shared atomics)
        if (lane == 0) {
            #pragma unroll
            for (int e = 0; e < EE; e++) {
                const bool is_in = noisyv[e] > v3;
                const float thr = is_in ? v3 : v2;
                const float p = phif((clean[e] - thr) / stdv[e]);
                atomicAdd(&s_load[e], p);
            }
            atomicAdd(&s_imp[i1], g1);
            atomicAdd(&s_imp[i2], g2);
        }

        // ---- Givens rotation + squared distance ----
        float d2[EE];
        #pragma unroll
        for (int e = 0; e < EE; e++) d2[e] = 0.0f;
        const float* rd = rel_diag + (size_t)q1 * DD;
        const float* rh = entity + (size_t)t2 * DD;
        for (int pg = lane; pg < NPAIR; pg += 32) {
            const int e = pg / 25;
            const int p = pg - 25 * e;
            const int k = e * RANKK + 2 * p;
            const float r0 = __ldg(rd + k), r1 = __ldg(rd + k + 1);
            float nrm = sqrtf(r0 * r0 + r1 * r1);
            nrm = fmaxf(nrm, 1e-15f);
            const float inv = 1.0f / nrm;
            const float c0 = r0 * inv, c1 = r1 * inv;
            const float x0 = sxw[k], x1 = sxw[k + 1];
            const float o0 = c0 * x0 - c1 * x1;
            const float o1 = c1 * x0 + c0 * x1;
            const float l0 = o0 + sxw[DD + e * (2 * RANKK) + 2 * p];
            const float l1 = o1 + sxw[DD + e * (2 * RANKK) + 2 * p + 1];
            const float u0 = l0 - __ldg(rh + k);
            const float u1 = l1 - __ldg(rh + k + 1);
            d2[e] = fmaf(u0, u0, fmaf(u1, u1, d2[e]));
        }
        #pragma unroll
        for (int off = 16; off > 0; off >>= 1) {
            #pragma unroll
            for (int e = 0; e < EE; e++)
                d2[e] += __shfl_xor_sync(0xffffffffu, d2[e], off);
        }

        // ---- score + masked logsumexp (mask = top-2 gates > 0) ----
        const float cc = softplusf(c_param[q1]);
        const float bsum = bh[q0] + bt[t2];
        const float sc1 = bsum - cc * d2[i1];
        const float sc2 = bsum - cc * d2[i2];
        float s = expf(sc1) + expf(sc2);
        if (s == 0.0f) s = 2.220446049250313e-16f;
        if (lane == 0) y_out[b] = logf(s);
    }

    __syncthreads();
    if (tid < EE) {
        atomicAdd(&g_load[tid], (double)s_load[tid]);
        atomicAdd(&g_imp[tid],  (double)s_imp[tid]);
    }
}

__global__ void loss_kernel(float* __restrict__ out, int idx) {
    if (threadIdx.x != 0 || blockIdx.x != 0) return;
    double mi = 0.0, ml = 0.0;
    for (int e = 0; e < EE; e++) { mi += g_imp[e]; ml += g_load[e]; }
    mi /= (double)EE; ml /= (double)EE;
    double vi = 0.0, vl = 0.0;
    for (int e = 0; e < EE; e++) {
        const double di = g_imp[e] - mi;  vi += di * di;
        const double dl = g_load[e] - ml; vl += dl * dl;
    }
    vi /= (double)(EE - 1); vl /= (double)(EE - 1);
    const double cvi = vi / (mi * mi + 1e-10);
    const double cvl = vl / (ml * ml + 1e-10);
    out[idx] = (float)(0.01 * (cvi + cvl));
}

extern "C" void kernel_launch(void* const* d_in, const int* in_sizes, int n_in,
                              void* d_out, int out_size) {
    const int*   queries       = (const int*)  d_in[0];
    const int*   these_queries = (const int*)  d_in[1];
    const float* entity        = (const float*)d_in[2];
    const float* rel           = (const float*)d_in[3];
    const float* rel_diag      = (const float*)d_in[4];
    const float* bh            = (const float*)d_in[5];
    const float* bt            = (const float*)d_in[6];
    const float* c_param       = (const float*)d_in[7];
    const float* cnn_w         = (const float*)d_in[8];
    const float* cnn_b         = (const float*)d_in[9];
    const float* h2e_w         = (const float*)d_in[10];
    const float* h2e_b         = (const float*)d_in[11];
    const float* cnnn_w        = (const float*)d_in[12];
    const float* cnnn_b        = (const float*)d_in[13];
    const float* h2en_w        = (const float*)d_in[14];
    const float* h2en_b        = (const float*)d_in[15];
    const float* noise         = (const float*)d_in[16];
    float* out = (float*)d_out;

    init_kernel<<<1, 32>>>();
    swise_main_kernel<<<NBLOCKS, 128>>>(
        queries, these_queries, entity, rel, rel_diag, bh, bt, c_param,
        cnn_w, cnn_b, h2e_w, h2e_b, cnnn_w, cnnn_b, h2en_w, h2en_b,
        noise, out);
    loss_kernel<<<1, 1>>>(out, out_size - 1);
}

// round 2
// speedup vs baseline: 1.0677x; 1.0677x over previous
#include <cuda_runtime.h>
#include <math.h>

#define BB 32768
#define EE 9
#define RANKK 50
#define DD 450            // E*RANK
#define XROWS 27
#define XSTRIDE 51        // padded row stride (conflict-free conv LDS)
#define WPB 4             // warps per block
#define ITER 8            // elements per warp
#define NBLOCKS (BB / (WPB * ITER))   // 1024

// per-block partials: [v*NBLOCKS + block], v = 0..8 load, 9..17 importance
__device__ float g_part[18 * NBLOCKS];

__device__ __forceinline__ float softplusf(float x) {
    if (x > 20.0f) return x;
    return log1pf(expf(x));
}
__device__ __forceinline__ float phif(float z) {
    return 0.5f * (1.0f + erff(z * 0.70710678118654752f));
}

__global__ __launch_bounds__(128) void swise_main_kernel(
    const int* __restrict__ queries, const int* __restrict__ these_queries,
    const float* __restrict__ entity, const float* __restrict__ rel,
    const float* __restrict__ rel_diag,
    const float* __restrict__ bh, const float* __restrict__ bt,
    const float* __restrict__ c_param,
    const float* __restrict__ cnn_w, const float* __restrict__ cnn_b,
    const float* __restrict__ h2e_w, const float* __restrict__ h2e_b,
    const float* __restrict__ cnnn_w, const float* __restrict__ cnnn_b,
    const float* __restrict__ h2en_w, const float* __restrict__ h2en_b,
    const float* __restrict__ noise, float* __restrict__ y_out)
{
    __shared__ float sx[WPB][XROWS * XSTRIDE];        // padded x image per warp
    __shared__ float swc[25], swn[25];
    __shared__ __align__(16) float sh2e[EE * 128];
    __shared__ __align__(16) float sh2en[EE * 128];
    __shared__ float sbc[2];
    __shared__ float sbe[EE], sben[EE];
    __shared__ float s_load[EE], s_imp[EE];

    const int tid = threadIdx.x;
    for (int i = tid; i < 25; i += blockDim.x) { swc[i] = cnn_w[i]; swn[i] = cnnn_w[i]; }
    for (int i = tid; i < EE * 128; i += blockDim.x) { sh2e[i] = h2e_w[i]; sh2en[i] = h2en_w[i]; }
    if (tid == 0) { sbc[0] = cnn_b[0]; sbc[1] = cnnn_b[0]; }
    if (tid < EE) { sbe[tid] = h2e_b[tid]; sben[tid] = h2en_b[tid];
                    s_load[tid] = 0.0f; s_imp[tid] = 0.0f; }
    __syncthreads();

    const int warp = tid >> 5, lane = tid & 31;
    const int ly = lane >> 2;          // oh  (0..7)
    const int lx = lane & 3;           // ow group (0..3), ow = 4*lx + q
    float* sxw = sx[warp];
    const int gw = blockIdx.x * WPB + warp;

    for (int it = 0; it < ITER; it++) {
        const int b = gw * ITER + it;
        const int q0 = queries[3 * b];
        const int q1 = queries[3 * b + 1];
        const int t2 = these_queries[3 * b + 2];

        __syncwarp();   // WAR: previous iteration's reads of sxw done

        // ---- stage x = [head rows 0..8 | rel rows 9..26] into padded shared ----
        const float2* hrow = (const float2*)(entity + (size_t)q0 * DD);
        for (int i = lane; i < 225; i += 32) {
            float2 v = __ldg(hrow + i);
            const int r = i / 25, c = (i - 25 * r) * 2;
            sxw[r * XSTRIDE + c] = v.x; sxw[r * XSTRIDE + c + 1] = v.y;
        }
        const float2* rrow = (const float2*)(rel + (size_t)q1 * (2 * DD));
        for (int i = lane; i < 450; i += 32) {
            float2 v = __ldg(rrow + i);
            const int r = 9 + i / 25, c = (i - 25 * (i / 25)) * 2;
            sxw[r * XSTRIDE + c] = v.x; sxw[r * XSTRIDE + c + 1] = v.y;
        }
        __syncwarp();

        // ---- conv (stride 3, VALID): each lane computes 4 consecutive ow ----
        float accc[4] = {0.f, 0.f, 0.f, 0.f};
        float accn[4] = {0.f, 0.f, 0.f, 0.f};
        #pragma unroll
        for (int kh = 0; kh < 5; kh++) {
            const float* rp = sxw + (3 * ly + kh) * XSTRIDE + 12 * lx;
            float row[14];
            #pragma unroll
            for (int j = 0; j < 14; j++) row[j] = rp[j];
            #pragma unroll
            for (int kw = 0; kw < 5; kw++) {
                const float wc = swc[kh * 5 + kw], wn = swn[kh * 5 + kw];
                #pragma unroll
                for (int q = 0; q < 4; q++) {
                    const float xv = row[3 * q + kw];
                    accc[q] = fmaf(xv, wc, accc[q]);
                    accn[q] = fmaf(xv, wn, accn[q]);
                }
            }
        }
        #pragma unroll
        for (int q = 0; q < 4; q++) { accc[q] += sbc[0]; accn[q] += sbc[1]; }

        // ---- fused linear: float4 weight loads, f_base = 16*ly + 4*lx ----
        const int f_base = 16 * ly + 4 * lx;
        float clean[EE], stdv[EE];
        #pragma unroll
        for (int e = 0; e < EE; e++) {
            const float4 wc4 = *(const float4*)&sh2e[e * 128 + f_base];
            const float4 wn4 = *(const float4*)&sh2en[e * 128 + f_base];
            float c0 = accc[0] * wc4.x; c0 = fmaf(accc[1], wc4.y, c0);
            c0 = fmaf(accc[2], wc4.z, c0); c0 = fmaf(accc[3], wc4.w, c0);
            float n0 = accn[0] * wn4.x; n0 = fmaf(accn[1], wn4.y, n0);
            n0 = fmaf(accn[2], wn4.z, n0); n0 = fmaf(accn[3], wn4.w, n0);
            clean[e] = c0; stdv[e] = n0;
        }
        #pragma unroll
        for (int off = 16; off > 0; off >>= 1) {
            #pragma unroll
            for (int e = 0; e < EE; e++) {
                clean[e] += __shfl_xor_sync(0xffffffffu, clean[e], off);
                stdv[e]  += __shfl_xor_sync(0xffffffffu, stdv[e], off);
            }
        }

        // ---- gating (uniform across lanes) ----
        float noisyv[EE];
        #pragma unroll
        for (int e = 0; e < EE; e++) {
            clean[e] += sbe[e];
            stdv[e] = softplusf(stdv[e] + sben[e]) + 0.01f;
            noisyv[e] = fmaf(noise[(size_t)b * EE + e], stdv[e], clean[e]);
        }
        int i1 = 0; float v1 = noisyv[0];
        #pragma unroll
        for (int e = 1; e < EE; e++) if (noisyv[e] > v1) { v1 = noisyv[e]; i1 = e; }
        int i2 = -1; float v2 = -INFINITY;
        #pragma unroll
        for (int e = 0; e < EE; e++) if (e != i1 && noisyv[e] > v2) { v2 = noisyv[e]; i2 = e; }
        float v3 = -INFINITY;
        #pragma unroll
        for (int e = 0; e < EE; e++) if (e != i1 && e != i2 && noisyv[e] > v3) v3 = noisyv[e];

        const float t_e = expf(v2 - v1);
        const float g1 = 1.0f / (1.0f + t_e);
        const float g2 = t_e / (1.0f + t_e);

        if (lane == 0) {
            #pragma unroll
            for (int e = 0; e < EE; e++) {
                const bool is_in = noisyv[e] > v3;
                const float thr = is_in ? v3 : v2;
                atomicAdd(&s_load[e], phif((clean[e] - thr) / stdv[e]));
            }
            atomicAdd(&s_imp[i1], g1);
            if (g2 > 0.0f) atomicAdd(&s_imp[i2], g2);
        }

        // ---- Givens + distance, ONLY for experts i1 and i2 (50 pairs) ----
        const float* rd = rel_diag + (size_t)q1 * DD;
        const float* rh = entity + (size_t)t2 * DD;
        float dA = 0.0f, dB = 0.0f;    // d2[i1], d2[i2]

        {   // item 1: widx = lane (0..31): experts i1 (p<25) or i2 (p-25)
            const bool sel = lane < 25;
            const int e = sel ? i1 : i2;
            const int p = sel ? lane : lane - 25;
            const int k = e * RANKK + 2 * p;
            const float2 r2 = __ldg((const float2*)(rd + e * RANKK) + p);
            const float2 h2v = __ldg((const float2*)(rh + e * RANKK) + p);
            const float inv = rsqrtf(fmaxf(r2.x * r2.x + r2.y * r2.y, 1e-30f));
            const float c0 = r2.x * inv, c1 = r2.y * inv;
            const float x0 = sxw[e * XSTRIDE + 2 * p];
            const float x1 = sxw[e * XSTRIDE + 2 * p + 1];
            const float rl0 = sxw[(9 + 2 * e) * XSTRIDE + 2 * p];
            const float rl1 = sxw[(9 + 2 * e) * XSTRIDE + 2 * p + 1];
            const float u0 = (c0 * x0 - c1 * x1) + rl0 - h2v.x;
            const float u1 = (c1 * x0 + c0 * x1) + rl1 - h2v.y;
            const float dd = fmaf(u0, u0, u1 * u1);
            if (sel) dA += dd; else dB += dd;
            (void)k;
        }
        if (lane < 18) {  // item 2: widx = lane + 32 (32..49): expert i2, p = lane+7
            const int p = lane + 7;
            const int e = i2;
            const float2 r2 = __ldg((const float2*)(rd + e * RANKK) + p);
            const float2 h2v = __ldg((const float2*)(rh + e * RANKK) + p);
            const float inv = rsqrtf(fmaxf(r2.x * r2.x + r2.y * r2.y, 1e-30f));
            const float c0 = r2.x * inv, c1 = r2.y * inv;
            const float x0 = sxw[e * XSTRIDE + 2 * p];
            const float x1 = sxw[e * XSTRIDE + 2 * p + 1];
            const float rl0 = sxw[(9 + 2 * e) * XSTRIDE + 2 * p];
            const float rl1 = sxw[(9 + 2 * e) * XSTRIDE + 2 * p + 1];
            const float u0 = (c0 * x0 - c1 * x1) + rl0 - h2v.x;
            const float u1 = (c1 * x0 + c0 * x1) + rl1 - h2v.y;
            dB = fmaf(u0, u0, fmaf(u1, u1, dB));
        }
        #pragma unroll
        for (int off = 16; off > 0; off >>= 1) {
            dA += __shfl_xor_sync(0xffffffffu, dA, off);
            dB += __shfl_xor_sync(0xffffffffu, dB, off);
        }

        // ---- score + masked logsumexp (mask = top-2 gates > 0) ----
        if (lane == 0) {
            const float cc = softplusf(c_param[q1]);
            const float bsum = bh[q0] + bt[t2];
            const float sc1 = bsum - cc * dA;
            const float sc2 = bsum - cc * dB;
            float s = expf(sc1) + (g2 > 0.0f ? expf(sc2) : 0.0f);
            if (s == 0.0f) s = 2.220446049250313e-16f;
            y_out[b] = logf(s);
        }
    }

    __syncthreads();
    if (tid < EE)       g_part[tid * NBLOCKS + blockIdx.x]        = s_load[tid];
    else if (tid < 18)  g_part[tid * NBLOCKS + blockIdx.x]        = s_imp[tid - 9];
}

__global__ __launch_bounds__(1024) void loss_kernel(float* __restrict__ out, int idx) {
    __shared__ double totals[18];
    __shared__ double wsum[18][32];
    const int tid = threadIdx.x;
    const int warp = tid >> 5, lane = tid & 31;
    if (tid < 18) totals[tid] = 0.0;
    __syncthreads();
    #pragma unroll
    for (int v = 0; v < 18; v++) {
        double val = (double)g_part[v * NBLOCKS + tid];
        #pragma unroll
        for (int off = 16; off > 0; off >>= 1)
            val += __shfl_xor_sync(0xffffffffu, val, off);
        if (lane == 0) wsum[v][warp] = val;
    }
    __syncthreads();
    if (warp == 0) {
        #pragma unroll
        for (int v = 0; v < 18; v++) {
            double val = wsum[v][lane];
            #pragma unroll
            for (int off = 16; off > 0; off >>= 1)
                val += __shfl_xor_sync(0xffffffffu, val, off);
            if (lane == 0) totals[v] = val;
        }
    }
    __syncthreads();
    if (tid == 0) {
        double ml = 0.0, mi = 0.0;
        for (int e = 0; e < EE; e++) { ml += totals[e]; mi += totals[9 + e]; }
        ml /= (double)EE; mi /= (double)EE;
        double vl = 0.0, vi = 0.0;
        for (int e = 0; e < EE; e++) {
            const double dl = totals[e] - ml;     vl += dl * dl;
            const double di = totals[9 + e] - mi; vi += di * di;
        }
        vl /= (double)(EE - 1); vi /= (double)(EE - 1);
        const double cvl = vl / (ml * ml + 1e-10);
        const double cvi = vi / (mi * mi + 1e-10);
        out[idx] = (float)(0.01 * (cvi + cvl));
    }
}

extern "C" void kernel_launch(void* const* d_in, const int* in_sizes, int n_in,
                              void* d_out, int out_size) {
    const int*   queries       = (const int*)  d_in[0];
    const int*   these_queries = (const int*)  d_in[1];
    const float* entity        = (const float*)d_in[2];
    const float* rel           = (const float*)d_in[3];
    const float* rel_diag      = (const float*)d_in[4];
    const float* bh            = (const float*)d_in[5];
    const float* bt            = (const float*)d_in[6];
    const float* c_param       = (const float*)d_in[7];
    const float* cnn_w         = (const float*)d_in[8];
    const float* cnn_b         = (const float*)d_in[9];
    const float* h2e_w         = (const float*)d_in[10];
    const float* h2e_b         = (const float*)d_in[11];
    const float* cnnn_w        = (const float*)d_in[12];
    const float* cnnn_b        = (const float*)d_in[13];
    const float* h2en_w        = (const float*)d_in[14];
    const float* h2en_b        = (const float*)d_in[15];
    const float* noise         = (const float*)d_in[16];
    float* out = (float*)d_out;

    swise_main_kernel<<<NBLOCKS, 128>>>(
        queries, these_queries, entity, rel, rel_diag, bh, bt, c_param,
        cnn_w, cnn_b, h2e_w, h2e_b, cnnn_w, cnnn_b, h2en_w, h2en_b,
        noise, out);
    loss_kernel<<<1, 1024>>>(out, out_size - 1);
}

// round 3
// speedup vs baseline: 1.4159x; 1.3261x over previous
#include <cuda_runtime.h>
#include <math.h>

#define BB 32768
#define EE 9
#define RANKK 50
#define DD 450            // E*RANK
#define XROWS 27
#define XSTRIDE 51        // padded row stride (conflict-free conv LDS)
#define WPB 4             // warps per block
#define ITER 8            // elements per warp
#define NBLOCKS (BB / (WPB * ITER))   // 1024

// per-block partials: [v*NBLOCKS + block], v = 0..8 load, 9..17 importance
__device__ float g_part[18 * NBLOCKS];
__device__ unsigned int g_count = 0;

__device__ __forceinline__ float softplusf(float x) {
    if (x > 20.0f) return x;
    return log1pf(expf(x));
}
__device__ __forceinline__ float phif(float z) {
    return 0.5f * (1.0f + erff(z * 0.70710678118654752f));
}

__global__ __launch_bounds__(128) void swise_main_kernel(
    const int* __restrict__ queries, const int* __restrict__ these_queries,
    const float* __restrict__ entity, const float* __restrict__ rel,
    const float* __restrict__ rel_diag,
    const float* __restrict__ bh, const float* __restrict__ bt,
    const float* __restrict__ c_param,
    const float* __restrict__ cnn_w, const float* __restrict__ cnn_b,
    const float* __restrict__ h2e_w, const float* __restrict__ h2e_b,
    const float* __restrict__ cnnn_w, const float* __restrict__ cnnn_b,
    const float* __restrict__ h2en_w, const float* __restrict__ h2en_b,
    const float* __restrict__ noise, float* __restrict__ y_out, int loss_idx)
{
    __shared__ float sx[WPB][XROWS * XSTRIDE];        // padded x image per warp
    __shared__ float swc[25], swn[25];
    __shared__ __align__(16) float sh2e[EE * 128];
    __shared__ __align__(16) float sh2en[EE * 128];
    __shared__ float sbc[2];
    __shared__ float sbe[EE], sben[EE];
    __shared__ float s_load[EE], s_imp[EE];
    __shared__ unsigned int s_is_last;
    __shared__ double totals[18];

    const int tid = threadIdx.x;
    for (int i = tid; i < 25; i += blockDim.x) { swc[i] = cnn_w[i]; swn[i] = cnnn_w[i]; }
    for (int i = tid; i < EE * 128; i += blockDim.x) { sh2e[i] = h2e_w[i]; sh2en[i] = h2en_w[i]; }
    if (tid == 0) { sbc[0] = cnn_b[0]; sbc[1] = cnnn_b[0]; }
    if (tid < EE) { sbe[tid] = h2e_b[tid]; sben[tid] = h2en_b[tid];
                    s_load[tid] = 0.0f; s_imp[tid] = 0.0f; }
    __syncthreads();

    const int warp = tid >> 5, lane = tid & 31;
    const int ly = lane >> 2;          // oh  (0..7)
    const int lx = lane & 3;           // ow group (0..3), ow = 4*lx + q
    float* sxw = sx[warp];
    const int gw = blockIdx.x * WPB + warp;

    for (int it = 0; it < ITER; it++) {
        const int b = gw * ITER + it;
        const int q0 = queries[3 * b];
        const int q1 = queries[3 * b + 1];
        const int t2 = these_queries[3 * b + 2];

        __syncwarp();   // WAR: previous iteration's reads of sxw done

        // ---- stage x = [head rows 0..8 | rel rows 9..26] into padded shared ----
        const float2* hrow = (const float2*)(entity + (size_t)q0 * DD);
        for (int i = lane; i < 225; i += 32) {
            float2 v = __ldg(hrow + i);
            const int r = i / 25, c = (i - 25 * r) * 2;
            sxw[r * XSTRIDE + c] = v.x; sxw[r * XSTRIDE + c + 1] = v.y;
        }
        const float2* rrow = (const float2*)(rel + (size_t)q1 * (2 * DD));
        for (int i = lane; i < 450; i += 32) {
            float2 v = __ldg(rrow + i);
            const int r = 9 + i / 25, c = (i - 25 * (i / 25)) * 2;
            sxw[r * XSTRIDE + c] = v.x; sxw[r * XSTRIDE + c + 1] = v.y;
        }
        __syncwarp();

        // ---- conv (stride 3, VALID): each lane computes 4 consecutive ow ----
        float accc[4] = {0.f, 0.f, 0.f, 0.f};
        float accn[4] = {0.f, 0.f, 0.f, 0.f};
        #pragma unroll
        for (int kh = 0; kh < 5; kh++) {
            const float* rp = sxw + (3 * ly + kh) * XSTRIDE + 12 * lx;
            float row[14];
            #pragma unroll
            for (int j = 0; j < 14; j++) row[j] = rp[j];
            #pragma unroll
            for (int kw = 0; kw < 5; kw++) {
                const float wc = swc[kh * 5 + kw], wn = swn[kh * 5 + kw];
                #pragma unroll
                for (int q = 0; q < 4; q++) {
                    const float xv = row[3 * q + kw];
                    accc[q] = fmaf(xv, wc, accc[q]);
                    accn[q] = fmaf(xv, wn, accn[q]);
                }
            }
        }
        #pragma unroll
        for (int q = 0; q < 4; q++) { accc[q] += sbc[0]; accn[q] += sbc[1]; }

        // ---- fused linear: float4 weight loads, f_base = 16*ly + 4*lx ----
        const int f_base = 16 * ly + 4 * lx;
        float clean[EE], stdv[EE];
        #pragma unroll
        for (int e = 0; e < EE; e++) {
            const float4 wc4 = *(const float4*)&sh2e[e * 128 + f_base];
            const float4 wn4 = *(const float4*)&sh2en[e * 128 + f_base];
            float c0 = accc[0] * wc4.x; c0 = fmaf(accc[1], wc4.y, c0);
            c0 = fmaf(accc[2], wc4.z, c0); c0 = fmaf(accc[3], wc4.w, c0);
            float n0 = accn[0] * wn4.x; n0 = fmaf(accn[1], wn4.y, n0);
            n0 = fmaf(accn[2], wn4.z, n0); n0 = fmaf(accn[3], wn4.w, n0);
            clean[e] = c0; stdv[e] = n0;
        }
        #pragma unroll
        for (int off = 16; off > 0; off >>= 1) {
            #pragma unroll
            for (int e = 0; e < EE; e++) {
                clean[e] += __shfl_xor_sync(0xffffffffu, clean[e], off);
                stdv[e]  += __shfl_xor_sync(0xffffffffu, stdv[e], off);
            }
        }

        // ---- gating (uniform across lanes) ----
        float noisyv[EE];
        #pragma unroll
        for (int e = 0; e < EE; e++) {
            clean[e] += sbe[e];
            stdv[e] = softplusf(stdv[e] + sben[e]) + 0.01f;
            noisyv[e] = fmaf(noise[(size_t)b * EE + e], stdv[e], clean[e]);
        }
        int i1 = 0; float v1 = noisyv[0];
        #pragma unroll
        for (int e = 1; e < EE; e++) if (noisyv[e] > v1) { v1 = noisyv[e]; i1 = e; }
        int i2 = -1; float v2 = -INFINITY;
        #pragma unroll
        for (int e = 0; e < EE; e++) if (e != i1 && noisyv[e] > v2) { v2 = noisyv[e]; i2 = e; }
        float v3 = -INFINITY;
        #pragma unroll
        for (int e = 0; e < EE; e++) if (e != i1 && e != i2 && noisyv[e] > v3) v3 = noisyv[e];

        const float t_e = expf(v2 - v1);
        const float g1 = 1.0f / (1.0f + t_e);
        const float g2 = t_e / (1.0f + t_e);

        if (lane == 0) {
            #pragma unroll
            for (int e = 0; e < EE; e++) {
                const bool is_in = noisyv[e] > v3;
                const float thr = is_in ? v3 : v2;
                atomicAdd(&s_load[e], phif((clean[e] - thr) / stdv[e]));
            }
            atomicAdd(&s_imp[i1], g1);
            if (g2 > 0.0f) atomicAdd(&s_imp[i2], g2);
        }

        // ---- Givens + distance, ONLY for experts i1 and i2 (50 pairs) ----
        const float* rd = rel_diag + (size_t)q1 * DD;
        const float* rh = entity + (size_t)t2 * DD;
        float dA = 0.0f, dB = 0.0f;    // d2[i1], d2[i2]

        {   // item 1: lanes 0..24 -> expert i1, lanes 25..31 -> expert i2
            const bool sel = lane < 25;
            const int e = sel ? i1 : i2;
            const int p = sel ? lane : lane - 25;
            const float2 r2 = __ldg((const float2*)(rd + e * RANKK) + p);
            const float2 h2v = __ldg((const float2*)(rh + e * RANKK) + p);
            const float inv = rsqrtf(fmaxf(r2.x * r2.x + r2.y * r2.y, 1e-30f));
            const float c0 = r2.x * inv, c1 = r2.y * inv;
            const float x0 = sxw[e * XSTRIDE + 2 * p];
            const float x1 = sxw[e * XSTRIDE + 2 * p + 1];
            const float rl0 = sxw[(9 + 2 * e) * XSTRIDE + 2 * p];
            const float rl1 = sxw[(9 + 2 * e) * XSTRIDE + 2 * p + 1];
            const float u0 = (c0 * x0 - c1 * x1) + rl0 - h2v.x;
            const float u1 = (c1 * x0 + c0 * x1) + rl1 - h2v.y;
            const float dd = fmaf(u0, u0, u1 * u1);
            if (sel) dA += dd; else dB += dd;
        }
        if (lane < 18) {  // item 2: expert i2, p = lane+7
            const int p = lane + 7;
            const int e = i2;
            const float2 r2 = __ldg((const float2*)(rd + e * RANKK) + p);
            const float2 h2v = __ldg((const float2*)(rh + e * RANKK) + p);
            const float inv = rsqrtf(fmaxf(r2.x * r2.x + r2.y * r2.y, 1e-30f));
            const float c0 = r2.x * inv, c1 = r2.y * inv;
            const float x0 = sxw[e * XSTRIDE + 2 * p];
            const float x1 = sxw[e * XSTRIDE + 2 * p + 1];
            const float rl0 = sxw[(9 + 2 * e) * XSTRIDE + 2 * p];
            const float rl1 = sxw[(9 + 2 * e) * XSTRIDE + 2 * p + 1];
            const float u0 = (c0 * x0 - c1 * x1) + rl0 - h2v.x;
            const float u1 = (c1 * x0 + c0 * x1) + rl1 - h2v.y;
            dB = fmaf(u0, u0, fmaf(u1, u1, dB));
        }
        #pragma unroll
        for (int off = 16; off > 0; off >>= 1) {
            dA += __shfl_xor_sync(0xffffffffu, dA, off);
            dB += __shfl_xor_sync(0xffffffffu, dB, off);
        }

        // ---- score + masked logsumexp (mask = top-2 gates > 0) ----
        if (lane == 0) {
            const float cc = softplusf(c_param[q1]);
            const float bsum = bh[q0] + bt[t2];
            const float sc1 = bsum - cc * dA;
            const float sc2 = bsum - cc * dB;
            float s = expf(sc1) + (g2 > 0.0f ? expf(sc2) : 0.0f);
            if (s == 0.0f) s = 2.220446049250313e-16f;
            y_out[b] = logf(s);
        }
    }

    __syncthreads();
    if (tid < EE)       g_part[tid * NBLOCKS + blockIdx.x] = s_load[tid];
    else if (tid < 18)  g_part[tid * NBLOCKS + blockIdx.x] = s_imp[tid - 9];
    __threadfence();
    if (tid == 0) {
        const unsigned int c = atomicAdd(&g_count, 1u);
        s_is_last = (c == NBLOCKS - 1) ? 1u : 0u;
    }
    __syncthreads();
    if (!s_is_last) return;

    // ---- last block: reduce 18 per-block partial vectors and emit loss ----
    for (int v = warp; v < 18; v += WPB) {
        float acc = 0.0f;
        #pragma unroll
        for (int j = 0; j < NBLOCKS / 32; j++)
            acc += g_part[v * NBLOCKS + j * 32 + lane];
        #pragma unroll
        for (int off = 16; off > 0; off >>= 1)
            acc += __shfl_xor_sync(0xffffffffu, acc, off);
        if (lane == 0) totals[v] = (double)acc;
    }
    __syncthreads();
    if (tid == 0) {
        double ml = 0.0, mi = 0.0;
        for (int e = 0; e < EE; e++) { ml += totals[e]; mi += totals[9 + e]; }
        ml /= (double)EE; mi /= (double)EE;
        double vl = 0.0, vi = 0.0;
        for (int e = 0; e < EE; e++) {
            const double dl = totals[e] - ml;     vl += dl * dl;
            const double di = totals[9 + e] - mi; vi += di * di;
        }
        vl /= (double)(EE - 1); vi /= (double)(EE - 1);
        const double cvl = vl / (ml * ml + 1e-10);
        const double cvi = vi / (mi * mi + 1e-10);
        y_out[loss_idx] = (float)(0.01 * (cvi + cvl));
        g_count = 0;   // reset for next graph replay (deterministic)
    }
}

extern "C" void kernel_launch(void* const* d_in, const int* in_sizes, int n_in,
                              void* d_out, int out_size) {
    const int*   queries       = (const int*)  d_in[0];
    const int*   these_queries = (const int*)  d_in[1];
    const float* entity        = (const float*)d_in[2];
    const float* rel           = (const float*)d_in[3];
    const float* rel_diag      = (const float*)d_in[4];
    const float* bh            = (const float*)d_in[5];
    const float* bt            = (const float*)d_in[6];
    const float* c_param       = (const float*)d_in[7];
    const float* cnn_w         = (const float*)d_in[8];
    const float* cnn_b         = (const float*)d_in[9];
    const float* h2e_w         = (const float*)d_in[10];
    const float* h2e_b         = (const float*)d_in[11];
    const float* cnnn_w        = (const float*)d_in[12];
    const float* cnnn_b        = (const float*)d_in[13];
    const float* h2en_w        = (const float*)d_in[14];
    const float* h2en_b        = (const float*)d_in[15];
    const float* noise         = (const float*)d_in[16];
    float* out = (float*)d_out;

    swise_main_kernel<<<NBLOCKS, 128>>>(
        queries, these_queries, entity, rel, rel_diag, bh, bt, c_param,
        cnn_w, cnn_b, h2e_w, h2e_b, cnnn_w, cnnn_b, h2en_w, h2en_b,
        noise, out, out_size - 1);
}

// round 4
// speedup vs baseline: 1.6986x; 1.1996x over previous
#include <cuda_runtime.h>
#include <math.h>

#define BB 32768
#define EE 9
#define RANKK 50
#define DD 450            // E*RANK
#define XROWS 27
#define XSTRIDE 51        // padded row stride (2-way max conflict on conv LDS)
#define WPB 8             // warps per block
#define ITER 4            // elements per warp
#define NBLOCKS (BB / (WPB * ITER * 1))   // 32768/32 = 1024

// per-block partials: [v*NBLOCKS + block], v = 0..8 load, 9..17 importance
__device__ float g_part[18 * NBLOCKS];
__device__ unsigned int g_count = 0;

__device__ __forceinline__ float softplusf(float x) {
    if (x > 20.0f) return x;
    return log1pf(expf(x));
}
__device__ __forceinline__ float phif(float z) {
    return 0.5f * (1.0f + erff(z * 0.70710678118654752f));
}

__global__ __launch_bounds__(256, 4) void swise_main_kernel(
    const int* __restrict__ queries, const int* __restrict__ these_queries,
    const float* __restrict__ entity, const float* __restrict__ rel,
    const float* __restrict__ rel_diag,
    const float* __restrict__ bh, const float* __restrict__ bt,
    const float* __restrict__ c_param,
    const float* __restrict__ cnn_w, const float* __restrict__ cnn_b,
    const float* __restrict__ h2e_w, const float* __restrict__ h2e_b,
    const float* __restrict__ cnnn_w, const float* __restrict__ cnnn_b,
    const float* __restrict__ h2en_w, const float* __restrict__ h2en_b,
    const float* __restrict__ noise, float* __restrict__ y_out, int loss_idx)
{
    __shared__ float sx[WPB][XROWS * XSTRIDE];        // padded x image per warp
    __shared__ float swc[25], swn[25];
    __shared__ __align__(16) float sh2e[EE * 128];
    __shared__ __align__(16) float sh2en[EE * 128];
    __shared__ float sbc[2];
    __shared__ float sbe[EE], sben[EE];
    __shared__ float s_load[EE], s_imp[EE];
    __shared__ unsigned int s_is_last;
    __shared__ double totals[18];

    const int tid = threadIdx.x;
    for (int i = tid; i < 25; i += blockDim.x) { swc[i] = cnn_w[i]; swn[i] = cnnn_w[i]; }
    for (int i = tid; i < EE * 128; i += blockDim.x) { sh2e[i] = h2e_w[i]; sh2en[i] = h2en_w[i]; }
    if (tid == 0) { sbc[0] = cnn_b[0]; sbc[1] = cnnn_b[0]; }
    if (tid < EE) { sbe[tid] = h2e_b[tid]; sben[tid] = h2en_b[tid];
                    s_load[tid] = 0.0f; s_imp[tid] = 0.0f; }
    __syncthreads();

    const int warp = tid >> 5, lane = tid & 31;
    const int ly = lane >> 2;          // oh  (0..7)
    const int lx = lane & 3;           // ow group (0..3), ow = 4*lx + q
    float* sxw = sx[warp];
    const int gw = blockIdx.x * WPB + warp;

    for (int it = 0; it < ITER; it++) {
        const int b = gw * ITER + it;
        const int q0 = queries[3 * b];
        const int q1 = queries[3 * b + 1];
        const int t2 = these_queries[3 * b + 2];

        __syncwarp();   // WAR: previous iteration's reads of sxw done

        // ---- stage x = [head rows 0..8 | rel rows 9..26] into padded shared ----
        const float2* hrow = (const float2*)(entity + (size_t)q0 * DD);
        for (int i = lane; i < 225; i += 32) {
            float2 v = __ldg(hrow + i);
            const int r = i / 25, c = (i - 25 * r) * 2;
            sxw[r * XSTRIDE + c] = v.x; sxw[r * XSTRIDE + c + 1] = v.y;
        }
        const float2* rrow = (const float2*)(rel + (size_t)q1 * (2 * DD));
        for (int i = lane; i < 450; i += 32) {
            float2 v = __ldg(rrow + i);
            const int r = 9 + i / 25, c = (i - 25 * (i / 25)) * 2;
            sxw[r * XSTRIDE + c] = v.x; sxw[r * XSTRIDE + c + 1] = v.y;
        }
        __syncwarp();

        // ---- conv (stride 3, VALID): each lane computes 4 consecutive ow ----
        float accc[4] = {0.f, 0.f, 0.f, 0.f};
        float accn[4] = {0.f, 0.f, 0.f, 0.f};
        #pragma unroll
        for (int kh = 0; kh < 5; kh++) {
            const float* rp = sxw + (3 * ly + kh) * XSTRIDE + 12 * lx;
            float row[14];
            #pragma unroll
            for (int j = 0; j < 14; j++) row[j] = rp[j];
            #pragma unroll
            for (int kw = 0; kw < 5; kw++) {
                const float wc = swc[kh * 5 + kw], wn = swn[kh * 5 + kw];
                #pragma unroll
                for (int q = 0; q < 4; q++) {
                    const float xv = row[3 * q + kw];
                    accc[q] = fmaf(xv, wc, accc[q]);
                    accn[q] = fmaf(xv, wn, accn[q]);
                }
            }
        }
        #pragma unroll
        for (int q = 0; q < 4; q++) { accc[q] += sbc[0]; accn[q] += sbc[1]; }

        // ---- fused linear: float4 weight loads, f_base = 16*ly + 4*lx ----
        const int f_base = 16 * ly + 4 * lx;
        float clean[EE], stdv[EE];
        #pragma unroll
        for (int e = 0; e < EE; e++) {
            const float4 wc4 = *(const float4*)&sh2e[e * 128 + f_base];
            const float4 wn4 = *(const float4*)&sh2en[e * 128 + f_base];
            float c0 = accc[0] * wc4.x; c0 = fmaf(accc[1], wc4.y, c0);
            c0 = fmaf(accc[2], wc4.z, c0); c0 = fmaf(accc[3], wc4.w, c0);
            float n0 = accn[0] * wn4.x; n0 = fmaf(accn[1], wn4.y, n0);
            n0 = fmaf(accn[2], wn4.z, n0); n0 = fmaf(accn[3], wn4.w, n0);
            clean[e] = c0; stdv[e] = n0;
        }
        // ---- split butterfly: round 1 routes clean->lanes<16, stdv->lanes>=16 ----
        const bool lowh = (lane < 16);
        float val[EE];
        #pragma unroll
        for (int e = 0; e < EE; e++) {
            const float oc = __shfl_xor_sync(0xffffffffu, clean[e], 16);
            const float os = __shfl_xor_sync(0xffffffffu, stdv[e], 16);
            val[e] = lowh ? (clean[e] + oc) : (stdv[e] + os);
        }
        #pragma unroll
        for (int off = 8; off > 0; off >>= 1) {
            #pragma unroll
            for (int e = 0; e < EE; e++)
                val[e] += __shfl_xor_sync(0xffffffffu, val[e], off);
        }
        #pragma unroll
        for (int e = 0; e < EE; e++) {
            const float other = __shfl_xor_sync(0xffffffffu, val[e], 16);
            clean[e] = lowh ? val[e] : other;
            stdv[e]  = lowh ? other  : val[e];
        }

        // ---- gating (uniform across lanes) ----
        float noisyv[EE];
        #pragma unroll
        for (int e = 0; e < EE; e++) {
            clean[e] += sbe[e];
            stdv[e] = softplusf(stdv[e] + sben[e]) + 0.01f;
            noisyv[e] = fmaf(noise[(size_t)b * EE + e], stdv[e], clean[e]);
        }
        int i1 = 0; float v1 = noisyv[0];
        #pragma unroll
        for (int e = 1; e < EE; e++) if (noisyv[e] > v1) { v1 = noisyv[e]; i1 = e; }
        int i2 = -1; float v2 = -INFINITY;
        #pragma unroll
        for (int e = 0; e < EE; e++) if (e != i1 && noisyv[e] > v2) { v2 = noisyv[e]; i2 = e; }
        float v3 = -INFINITY;
        #pragma unroll
        for (int e = 0; e < EE; e++) if (e != i1 && e != i2 && noisyv[e] > v3) v3 = noisyv[e];

        const float t_e = expf(v2 - v1);
        const float g1 = 1.0f / (1.0f + t_e);
        const float g2 = t_e / (1.0f + t_e);

        // prob/load: one expert per lane (parallel erf, conflict-free atomics)
        if (lane < EE) {
            float ce = 0.0f, se = 1.0f, ne = 0.0f;
            #pragma unroll
            for (int e = 0; e < EE; e++)
                if (lane == e) { ce = clean[e]; se = stdv[e]; ne = noisyv[e]; }
            const float thr = (ne > v3) ? v3 : v2;
            atomicAdd(&s_load[lane], phif((ce - thr) / se));
        }
        if (lane == 0) {
            atomicAdd(&s_imp[i1], g1);
            if (g2 > 0.0f) atomicAdd(&s_imp[i2], g2);
        }

        // ---- Givens + distance, ONLY for experts i1 and i2 (50 pairs) ----
        const float* rd = rel_diag + (size_t)q1 * DD;
        const float* rh = entity + (size_t)t2 * DD;
        float dA = 0.0f, dB = 0.0f;    // d2[i1], d2[i2]

        {   // item 1: lanes 0..24 -> expert i1, lanes 25..31 -> expert i2
            const bool sel = lane < 25;
            const int e = sel ? i1 : i2;
            const int p = sel ? lane : lane - 25;
            const float2 r2 = __ldg((const float2*)(rd + e * RANKK) + p);
            const float2 h2v = __ldg((const float2*)(rh + e * RANKK) + p);
            const float inv = rsqrtf(fmaxf(r2.x * r2.x + r2.y * r2.y, 1e-30f));
            const float c0 = r2.x * inv, c1 = r2.y * inv;
            const float x0 = sxw[e * XSTRIDE + 2 * p];
            const float x1 = sxw[e * XSTRIDE + 2 * p + 1];
            const float rl0 = sxw[(9 + 2 * e) * XSTRIDE + 2 * p];
            const float rl1 = sxw[(9 + 2 * e) * XSTRIDE + 2 * p + 1];
            const float u0 = (c0 * x0 - c1 * x1) + rl0 - h2v.x;
            const float u1 = (c1 * x0 + c0 * x1) + rl1 - h2v.y;
            const float dd = fmaf(u0, u0, u1 * u1);
            if (sel) dA += dd; else dB += dd;
        }
        if (lane < 18) {  // item 2: expert i2, p = lane+7
            const int p = lane + 7;
            const int e = i2;
            const float2 r2 = __ldg((const float2*)(rd + e * RANKK) + p);
            const float2 h2v = __ldg((const float2*)(rh + e * RANKK) + p);
            const float inv = rsqrtf(fmaxf(r2.x * r2.x + r2.y * r2.y, 1e-30f));
            const float c0 = r2.x * inv, c1 = r2.y * inv;
            const float x0 = sxw[e * XSTRIDE + 2 * p];
            const float x1 = sxw[e * XSTRIDE + 2 * p + 1];
            const float rl0 = sxw[(9 + 2 * e) * XSTRIDE + 2 * p];
            const float rl1 = sxw[(9 + 2 * e) * XSTRIDE + 2 * p + 1];
            const float u0 = (c0 * x0 - c1 * x1) + rl0 - h2v.x;
            const float u1 = (c1 * x0 + c0 * x1) + rl1 - h2v.y;
            dB = fmaf(u0, u0, fmaf(u1, u1, dB));
        }
        #pragma unroll
        for (int off = 16; off > 0; off >>= 1) {
            dA += __shfl_xor_sync(0xffffffffu, dA, off);
            dB += __shfl_xor_sync(0xffffffffu, dB, off);
        }

        // ---- score + masked logsumexp (mask = top-2 gates > 0) ----
        if (lane == 0) {
            const float cc = softplusf(c_param[q1]);
            const float bsum = bh[q0] + bt[t2];
            const float sc1 = bsum - cc * dA;
            const float sc2 = bsum - cc * dB;
            float s = expf(sc1) + (g2 > 0.0f ? expf(sc2) : 0.0f);
            if (s == 0.0f) s = 2.220446049250313e-16f;
            y_out[b] = logf(s);
        }
    }

    __syncthreads();
    if (tid < EE)       g_part[tid * NBLOCKS + blockIdx.x] = s_load[tid];
    else if (tid < 18)  g_part[tid * NBLOCKS + blockIdx.x] = s_imp[tid - 9];
    __threadfence();
    if (tid == 0) {
        const unsigned int c = atomicAdd(&g_count, 1u);
        s_is_last = (c == NBLOCKS - 1) ? 1u : 0u;
    }
    __syncthreads();
    if (!s_is_last) return;

    // ---- last block: reduce 18 per-block partial vectors and emit loss ----
    for (int v = warp; v < 18; v += WPB) {
        float acc = 0.0f;
        #pragma unroll
        for (int j = 0; j < NBLOCKS / 32; j++)
            acc += g_part[v * NBLOCKS + j * 32 + lane];
        #pragma unroll
        for (int off = 16; off > 0; off >>= 1)
            acc += __shfl_xor_sync(0xffffffffu, acc, off);
        if (lane == 0) totals[v] = (double)acc;
    }
    __syncthreads();
    if (tid == 0) {
        double ml = 0.0, mi = 0.0;
        for (int e = 0; e < EE; e++) { ml += totals[e]; mi += totals[9 + e]; }
        ml /= (double)EE; mi /= (double)EE;
        double vl = 0.0, vi = 0.0;
        for (int e = 0; e < EE; e++) {
            const double dl = totals[e] - ml;     vl += dl * dl;
            const double di = totals[9 + e] - mi; vi += di * di;
        }
        vl /= (double)(EE - 1); vi /= (double)(EE - 1);
        const double cvl = vl / (ml * ml + 1e-10);
        const double cvi = vi / (mi * mi + 1e-10);
        y_out[loss_idx] = (float)(0.01 * (cvi + cvl));
        g_count = 0;   // reset for next graph replay (deterministic)
    }
}

extern "C" void kernel_launch(void* const* d_in, const int* in_sizes, int n_in,
                              void* d_out, int out_size) {
    const int*   queries       = (const int*)  d_in[0];
    const int*   these_queries = (const int*)  d_in[1];
    const float* entity        = (const float*)d_in[2];
    const float* rel           = (const float*)d_in[3];
    const float* rel_diag      = (const float*)d_in[4];
    const float* bh            = (const float*)d_in[5];
    const float* bt            = (const float*)d_in[6];
    const float* c_param       = (const float*)d_in[7];
    const float* cnn_w         = (const float*)d_in[8];
    const float* cnn_b         = (const float*)d_in[9];
    const float* h2e_w         = (const float*)d_in[10];
    const float* h2e_b         = (const float*)d_in[11];
    const float* cnnn_w        = (const float*)d_in[12];
    const float* cnnn_b        = (const float*)d_in[13];
    const float* h2en_w        = (const float*)d_in[14];
    const float* h2en_b        = (const float*)d_in[15];
    const float* noise         = (const float*)d_in[16];
    float* out = (float*)d_out;

    swise_main_kernel<<<NBLOCKS, 256>>>(
        queries, these_queries, entity, rel, rel_diag, bh, bt, c_param,
        cnn_w, cnn_b, h2e_w, h2e_b, cnnn_w, cnnn_b, h2en_w, h2en_b,
        noise, out, out_size - 1);
}

// round 5
// speedup vs baseline: 1.9082x; 1.1234x over previous
#include <cuda_runtime.h>
#include <math.h>

#define BB 32768
#define EE 9
#define RANKK 50
#define DD 450            // E*RANK
#define WPB 8             // warps per block
#define NB 592            // persistent grid: 148 SMs x 4 blocks
#define NBP 608           // padded partial stride (pad slots stay zero)
#define TOTW (NB * WPB)   // 4736 warps
#define XOFF 2            // head starts at sxw[2] so rel (sxw[452]) is 16B-aligned
#define XSZ 1352          // 2 + 450 + 900

// per-block partials: [v*NBP + block], v = 0..8 load, 9..17 importance
__device__ float g_part[18 * NBP];
__device__ unsigned int g_count = 0;

__device__ __forceinline__ float softplusf(float x) {
    if (x > 20.0f) return x;
    return log1pf(expf(x));
}
__device__ __forceinline__ float phif(float z) {
    return 0.5f * (1.0f + erff(z * 0.70710678118654752f));
}

__global__ __launch_bounds__(256, 4) void swise_main_kernel(
    const int* __restrict__ queries, const int* __restrict__ these_queries,
    const float* __restrict__ entity, const float* __restrict__ rel,
    const float* __restrict__ rel_diag,
    const float* __restrict__ bh, const float* __restrict__ bt,
    const float* __restrict__ c_param,
    const float* __restrict__ cnn_w, const float* __restrict__ cnn_b,
    const float* __restrict__ h2e_w, const float* __restrict__ h2e_b,
    const float* __restrict__ cnnn_w, const float* __restrict__ cnnn_b,
    const float* __restrict__ h2en_w, const float* __restrict__ h2en_b,
    const float* __restrict__ noise, float* __restrict__ y_out, int loss_idx)
{
    __shared__ __align__(16) float sx[WPB][XSZ];   // x image per warp, contiguous
    __shared__ float swc[25], swn[25];
    __shared__ __align__(16) float sh2e[EE * 128];
    __shared__ __align__(16) float sh2en[EE * 128];
    __shared__ float sbc[2];
    __shared__ float sbe[EE], sben[EE];
    __shared__ float s_load[EE], s_imp[EE];
    __shared__ unsigned int s_is_last;
    __shared__ double totals[18];

    const int tid = threadIdx.x;
    for (int i = tid; i < 25; i += blockDim.x) { swc[i] = cnn_w[i]; swn[i] = cnnn_w[i]; }
    for (int i = tid; i < EE * 128; i += blockDim.x) { sh2e[i] = h2e_w[i]; sh2en[i] = h2en_w[i]; }
    if (tid == 0) { sbc[0] = cnn_b[0]; sbc[1] = cnnn_b[0]; }
    if (tid < EE) { sbe[tid] = h2e_b[tid]; sben[tid] = h2en_b[tid];
                    s_load[tid] = 0.0f; s_imp[tid] = 0.0f; }
    __syncthreads();

    const int warp = tid >> 5, lane = tid & 31;
    const int ly = lane >> 2;          // oh  (0..7)
    const int lx = lane & 3;           // ow group (0..3), ow = 4*lx + q
    float* sxw = sx[warp];
    const int gw = blockIdx.x * WPB + warp;

    for (int b = gw; b < BB; b += TOTW) {
        const int q0 = queries[3 * b];
        const int q1 = queries[3 * b + 1];
        const int t2 = these_queries[3 * b + 2];

        __syncwarp();   // WAR: previous iteration's reads of sxw done

        // ---- stage x = [head | rel] contiguous at sxw+XOFF ----
        const float2* hrow = (const float2*)(entity + (size_t)q0 * DD);
        #pragma unroll
        for (int t = 0; t < 8; t++) {
            const int i = lane + 32 * t;
            if (i < 225) {
                const float2 v = __ldg(hrow + i);
                *(float2*)&sxw[XOFF + 2 * i] = v;
            }
        }
        const float4* rrow = (const float4*)(rel + (size_t)q1 * (2 * DD));
        #pragma unroll
        for (int t = 0; t < 8; t++) {
            const int i = lane + 32 * t;
            if (i < 225) {
                const float4 v = __ldg(rrow + i);
                *(float4*)&sxw[XOFF + DD + 4 * i] = v;
            }
        }
        __syncwarp();

        // ---- conv (stride 3, VALID): each lane computes 4 consecutive ow ----
        float accc[4] = {0.f, 0.f, 0.f, 0.f};
        float accn[4] = {0.f, 0.f, 0.f, 0.f};
        #pragma unroll
        for (int kh = 0; kh < 5; kh++) {
            const float* rp = sxw + XOFF + (3 * ly + kh) * RANKK + 12 * lx;
            float row[14];
            #pragma unroll
            for (int j2 = 0; j2 < 7; j2++) {
                const float2 t = *(const float2*)(rp + 2 * j2);
                row[2 * j2] = t.x; row[2 * j2 + 1] = t.y;
            }
            #pragma unroll
            for (int kw = 0; kw < 5; kw++) {
                const float wc = swc[kh * 5 + kw], wn = swn[kh * 5 + kw];
                #pragma unroll
                for (int q = 0; q < 4; q++) {
                    const float xv = row[3 * q + kw];
                    accc[q] = fmaf(xv, wc, accc[q]);
                    accn[q] = fmaf(xv, wn, accn[q]);
                }
            }
        }
        #pragma unroll
        for (int q = 0; q < 4; q++) { accc[q] += sbc[0]; accn[q] += sbc[1]; }

        // ---- fused linear: float4 weight loads, f_base = 16*ly + 4*lx ----
        const int f_base = 16 * ly + 4 * lx;
        float clean[EE], stdv[EE];
        #pragma unroll
        for (int e = 0; e < EE; e++) {
            const float4 wc4 = *(const float4*)&sh2e[e * 128 + f_base];
            const float4 wn4 = *(const float4*)&sh2en[e * 128 + f_base];
            float c0 = accc[0] * wc4.x; c0 = fmaf(accc[1], wc4.y, c0);
            c0 = fmaf(accc[2], wc4.z, c0); c0 = fmaf(accc[3], wc4.w, c0);
            float n0 = accn[0] * wn4.x; n0 = fmaf(accn[1], wn4.y, n0);
            n0 = fmaf(accn[2], wn4.z, n0); n0 = fmaf(accn[3], wn4.w, n0);
            clean[e] = c0; stdv[e] = n0;
        }
        // ---- split butterfly: round 1 routes clean->lanes<16, stdv->lanes>=16 ----
        const bool lowh = (lane < 16);
        float val[EE];
        #pragma unroll
        for (int e = 0; e < EE; e++) {
            const float oc = __shfl_xor_sync(0xffffffffu, clean[e], 16);
            const float os = __shfl_xor_sync(0xffffffffu, stdv[e], 16);
            val[e] = lowh ? (clean[e] + oc) : (stdv[e] + os);
        }
        #pragma unroll
        for (int off = 8; off > 0; off >>= 1) {
            #pragma unroll
            for (int e = 0; e < EE; e++)
                val[e] += __shfl_xor_sync(0xffffffffu, val[e], off);
        }
        #pragma unroll
        for (int e = 0; e < EE; e++) {
            const float other = __shfl_xor_sync(0xffffffffu, val[e], 16);
            clean[e] = lowh ? val[e] : other;
            stdv[e]  = lowh ? other  : val[e];
        }

        // ---- gating (uniform across lanes) ----
        float noisyv[EE];
        #pragma unroll
        for (int e = 0; e < EE; e++) {
            clean[e] += sbe[e];
            stdv[e] = softplusf(stdv[e] + sben[e]) + 0.01f;
            noisyv[e] = fmaf(noise[(size_t)b * EE + e], stdv[e], clean[e]);
        }
        int i1 = 0; float v1 = noisyv[0];
        #pragma unroll
        for (int e = 1; e < EE; e++) if (noisyv[e] > v1) { v1 = noisyv[e]; i1 = e; }
        int i2 = -1; float v2 = -INFINITY;
        #pragma unroll
        for (int e = 0; e < EE; e++) if (e != i1 && noisyv[e] > v2) { v2 = noisyv[e]; i2 = e; }
        float v3 = -INFINITY;
        #pragma unroll
        for (int e = 0; e < EE; e++) if (e != i1 && e != i2 && noisyv[e] > v3) v3 = noisyv[e];

        const float t_e = expf(v2 - v1);
        const float g1 = 1.0f / (1.0f + t_e);
        const float g2 = t_e / (1.0f + t_e);

        // prob/load: one expert per lane (parallel erf, conflict-free atomics)
        if (lane < EE) {
            float ce = 0.0f, se = 1.0f, ne = 0.0f;
            #pragma unroll
            for (int e = 0; e < EE; e++)
                if (lane == e) { ce = clean[e]; se = stdv[e]; ne = noisyv[e]; }
            const float thr = (ne > v3) ? v3 : v2;
            atomicAdd(&s_load[lane], phif((ce - thr) / se));
        }
        if (lane == 0) {
            atomicAdd(&s_imp[i1], g1);
            if (g2 > 0.0f) atomicAdd(&s_imp[i2], g2);
        }

        // ---- Givens + distance, ONLY for experts i1 and i2 (50 pairs) ----
        const float* rd = rel_diag + (size_t)q1 * DD;
        const float* rh = entity + (size_t)t2 * DD;
        float dA = 0.0f, dB = 0.0f;    // d2[i1], d2[i2]

        {   // item 1: lanes 0..24 -> expert i1, lanes 25..31 -> expert i2
            const bool sel = lane < 25;
            const int e = sel ? i1 : i2;
            const int p = sel ? lane : lane - 25;
            const float2 r2 = __ldg((const float2*)(rd + e * RANKK) + p);
            const float2 h2v = __ldg((const float2*)(rh + e * RANKK) + p);
            const float inv = rsqrtf(fmaxf(r2.x * r2.x + r2.y * r2.y, 1e-30f));
            const float c0 = r2.x * inv, c1 = r2.y * inv;
            const float x0 = sxw[XOFF + e * RANKK + 2 * p];
            const float x1 = sxw[XOFF + e * RANKK + 2 * p + 1];
            const float rl0 = sxw[XOFF + DD + e * (2 * RANKK) + 2 * p];
            const float rl1 = sxw[XOFF + DD + e * (2 * RANKK) + 2 * p + 1];
            const float u0 = (c0 * x0 - c1 * x1) + rl0 - h2v.x;
            const float u1 = (c1 * x0 + c0 * x1) + rl1 - h2v.y;
            const float dd = fmaf(u0, u0, u1 * u1);
            if (sel) dA += dd; else dB += dd;
        }
        if (lane < 18) {  // item 2: expert i2, p = lane+7
            const int p = lane + 7;
            const int e = i2;
            const float2 r2 = __ldg((const float2*)(rd + e * RANKK) + p);
            const float2 h2v = __ldg((const float2*)(rh + e * RANKK) + p);
            const float inv = rsqrtf(fmaxf(r2.x * r2.x + r2.y * r2.y, 1e-30f));
            const float c0 = r2.x * inv, c1 = r2.y * inv;
            const float x0 = sxw[XOFF + e * RANKK + 2 * p];
            const float x1 = sxw[XOFF + e * RANKK + 2 * p + 1];
            const float rl0 = sxw[XOFF + DD + e * (2 * RANKK) + 2 * p];
            const float rl1 = sxw[XOFF + DD + e * (2 * RANKK) + 2 * p + 1];
            const float u0 = (c0 * x0 - c1 * x1) + rl0 - h2v.x;
            const float u1 = (c1 * x0 + c0 * x1) + rl1 - h2v.y;
            dB = fmaf(u0, u0, fmaf(u1, u1, dB));
        }
        #pragma unroll
        for (int off = 16; off > 0; off >>= 1) {
            dA += __shfl_xor_sync(0xffffffffu, dA, off);
            dB += __shfl_xor_sync(0xffffffffu, dB, off);
        }

        // ---- score + masked logsumexp (mask = top-2 gates > 0) ----
        if (lane == 0) {
            const float cc = softplusf(c_param[q1]);
            const float bsum = bh[q0] + bt[t2];
            const float sc1 = bsum - cc * dA;
            const float sc2 = bsum - cc * dB;
            float s = expf(sc1) + (g2 > 0.0f ? expf(sc2) : 0.0f);
            if (s == 0.0f) s = 2.220446049250313e-16f;
            y_out[b] = logf(s);
        }
    }

    __syncthreads();
    if (tid < EE)       g_part[tid * NBP + blockIdx.x] = s_load[tid];
    else if (tid < 18)  g_part[tid * NBP + blockIdx.x] = s_imp[tid - 9];
    __threadfence();
    if (tid == 0) {
        const unsigned int c = atomicAdd(&g_count, 1u);
        s_is_last = (c == NB - 1) ? 1u : 0u;
    }
    __syncthreads();
    if (!s_is_last) return;

    // ---- last block: reduce 18 per-block partial vectors and emit loss ----
    for (int v = warp; v < 18; v += WPB) {
        float acc = 0.0f;
        #pragma unroll
        for (int j = 0; j < 19; j++)          // 19*32 = 608 = NBP (pads are zero)
            acc += g_part[v * NBP + j * 32 + lane];
        #pragma unroll
        for (int off = 16; off > 0; off >>= 1)
            acc += __shfl_xor_sync(0xffffffffu, acc, off);
        if (lane == 0) totals[v] = (double)acc;
    }
    __syncthreads();
    if (tid == 0) {
        double ml = 0.0, mi = 0.0;
        for (int e = 0; e < EE; e++) { ml += totals[e]; mi += totals[9 + e]; }
        ml /= (double)EE; mi /= (double)EE;
        double vl = 0.0, vi = 0.0;
        for (int e = 0; e < EE; e++) {
            const double dl = totals[e] - ml;     vl += dl * dl;
            const double di = totals[9 + e] - mi; vi += di * di;
        }
        vl /= (double)(EE - 1); vi /= (double)(EE - 1);
        const double cvl = vl / (ml * ml + 1e-10);
        const double cvi = vi / (mi * mi + 1e-10);
        y_out[loss_idx] = (float)(0.01 * (cvi + cvl));
        g_count = 0;   // reset for next graph replay (deterministic)
    }
}

extern "C" void kernel_launch(void* const* d_in, const int* in_sizes, int n_in,
                              void* d_out, int out_size) {
    const int*   queries       = (const int*)  d_in[0];
    const int*   these_queries = (const int*)  d_in[1];
    const float* entity        = (const float*)d_in[2];
    const float* rel           = (const float*)d_in[3];
    const float* rel_diag      = (const float*)d_in[4];
    const float* bh            = (const float*)d_in[5];
    const float* bt            = (const float*)d_in[6];
    const float* c_param       = (const float*)d_in[7];
    const float* cnn_w         = (const float*)d_in[8];
    const float* cnn_b         = (const float*)d_in[9];
    const float* h2e_w         = (const float*)d_in[10];
    const float* h2e_b         = (const float*)d_in[11];
    const float* cnnn_w        = (const float*)d_in[12];
    const float* cnnn_b        = (const float*)d_in[13];
    const float* h2en_w        = (const float*)d_in[14];
    const float* h2en_b        = (const float*)d_in[15];
    const float* noise         = (const float*)d_in[16];
    float* out = (float*)d_out;

    swise_main_kernel<<<NB, 256>>>(
        queries, these_queries, entity, rel, rel_diag, bh, bt, c_param,
        cnn_w, cnn_b, h2e_w, h2e_b, cnnn_w, cnnn_b, h2en_w, h2en_b,
        noise, out, out_size - 1);
}